// round 1
// baseline (speedup 1.0000x reference)
#include <cuda_runtime.h>

// out[b] = dot(user_factors[users[b]], item_factors[items[b]]), D = 64.
// One warp per batch element. Lane L loads float2 #L of each 64-float row
// (256 B coalesced per row), FMAs, then butterfly-reduces across the warp.

#define D 64
#define WARPS_PER_BLOCK 8
#define THREADS (WARPS_PER_BLOCK * 32)

__global__ __launch_bounds__(THREADS)
void mf_dot_kernel(const int* __restrict__ users,
                   const int* __restrict__ items,
                   const float* __restrict__ user_factors,
                   const float* __restrict__ item_factors,
                   float* __restrict__ out,
                   int batch)
{
    int warp_id = (blockIdx.x * WARPS_PER_BLOCK) + (threadIdx.x >> 5);
    int lane = threadIdx.x & 31;
    if (warp_id >= batch) return;

    int u_idx = __ldg(&users[warp_id]);
    int i_idx = __ldg(&items[warp_id]);

    const float2* u_row = reinterpret_cast<const float2*>(user_factors + (long long)u_idx * D);
    const float2* v_row = reinterpret_cast<const float2*>(item_factors + (long long)i_idx * D);

    float2 u = __ldg(&u_row[lane]);
    float2 v = __ldg(&v_row[lane]);

    float acc = fmaf(u.x, v.x, u.y * v.y);

    // Warp butterfly reduction
    #pragma unroll
    for (int off = 16; off > 0; off >>= 1)
        acc += __shfl_xor_sync(0xFFFFFFFFu, acc, off);

    if (lane == 0)
        out[warp_id] = acc;
}

extern "C" void kernel_launch(void* const* d_in, const int* in_sizes, int n_in,
                              void* d_out, int out_size)
{
    const int*   users        = (const int*)  d_in[0];
    const int*   items        = (const int*)  d_in[1];
    const float* user_factors = (const float*)d_in[2];
    const float* item_factors = (const float*)d_in[3];
    float*       out          = (float*)      d_out;

    int batch = in_sizes[0];
    int blocks = (batch + WARPS_PER_BLOCK - 1) / WARPS_PER_BLOCK;
    mf_dot_kernel<<<blocks, THREADS>>>(users, items, user_factors, item_factors, out, batch);
}